// round 14
// baseline (speedup 1.0000x reference)
#include <cuda_runtime.h>
#include <math.h>

// Problem constants
#define M    129         // mesh points per dim (odd)
#define MH   65          // half-spectrum rows: k1 = 0..64
#define NB   4           // batch
#define NP   512         // points per batch
#define NPTS (NB*NP)     // 2048
#define WSUP 7           // gaussian support half-width (tail at d=8 ~ 1e-23)
#define NW   15          // taps = 2*WSUP+1
#define RJ   5           // k1 rows per k_S block (13*5 = 65)
#define PCH  64          // points per k_S chunk (512/64 = 8 chunks)
#define NCH  8

// Scratch (__device__ globals: no allocations allowed)
__device__ float2 g_Gx[NPTS*MH];          // per-point x-spectrum, k1 = 0..64
__device__ float2 g_Gy[NPTS*M];           // per-point y-spectrum, k2 = -64..64 (j2 = k2+64)
__device__ float2 g_Spart[NCH*NB*MH*M];   // partial per-batch spectrum sums (8 chunks)
__device__ float4 g_SD[NB*MH*M];          // packed (S.re, S.im, D0, D1) per batch & k-point

// ---------------------------------------------------------------- f32x2 helpers
__device__ __forceinline__ unsigned long long f2_fma(unsigned long long a, unsigned long long b,
                                                     unsigned long long c) {
    unsigned long long d;
    asm("fma.rn.f32x2 %0, %1, %2, %3;" : "=l"(d) : "l"(a), "l"(b), "l"(c));
    return d;
}
__device__ __forceinline__ unsigned long long f2_mul(unsigned long long a, unsigned long long b) {
    unsigned long long d;
    asm("mul.rn.f32x2 %0, %1, %2;" : "=l"(d) : "l"(a), "l"(b));
    return d;
}
__device__ __forceinline__ unsigned long long f2_pack(float lo, float hi) {
    unsigned long long d;
    asm("mov.b64 %0, {%1, %2};" : "=l"(d) : "f"(lo), "f"(hi));
    return d;
}
__device__ __forceinline__ void f2_unpack(float& lo, float& hi, unsigned long long v) {
    asm("mov.b64 {%0, %1}, %2;" : "=f"(lo), "=f"(hi) : "l"(v));
}

// ---------------------------------------------------------------- per-point 1D spectra
__device__ __forceinline__ float gper(float x) {
    const float INV4 = (float)(129.0 * 129.0 / 48.0);   // 1/(4*tau), tau = 12/M^2
    const float L    = (float)(2.0 * 3.14159265358979323846);
    return expf(-x * x * INV4)
         + expf(-(x - L) * (x - L) * INV4)
         + expf(-(x + L) * (x + L) * INV4);
}

__global__ void k_spectra(const float* __restrict__ X) {
    int p   = blockIdx.x;       // global point index 0..2047
    int tid = threadIdx.x;      // 128 threads
    __shared__ float2 cis[M];   // exp(-2*pi*i*t/M)
    __shared__ float  wgt[2][NW];

    for (int t = tid; t < M; t += 128) {
        float ang = (float)t * (float)(-2.0 * 3.14159265358979323846 / 129.0);
        float s, c;
        sincosf(ang, &s, &c);
        cis[t] = make_float2(c, s);
    }

    float x0 = X[2 * p];
    float y0 = X[2 * p + 1];
    const float H    = (float)(2.0 * 3.14159265358979323846 / 129.0);
    const float INVH = (float)(129.0 / (2.0 * 3.14159265358979323846));
    int i0x = (int)floorf(x0 * INVH + 0.5f);
    int i0y = (int)floorf(y0 * INVH + 0.5f);

    if (tid < 2 * NW) {
        int dim = tid / NW;
        int d   = tid - dim * NW;
        float xv = dim ? y0 : x0;
        int   i0 = dim ? i0y : i0x;
        int i  = i0 - WSUP + d;
        int iw = i % M; if (iw < 0) iw += M;        // wrapped grid index (matches reference arg)
        wgt[dim][d] = gper(xv - (float)iw * H);
    }
    __syncthreads();

    // 65 x-outputs (k=0..64) + 129 y-outputs (k=-64..64)
    for (int o = tid; o < MH + M; o += 128) {
        bool isX = (o < MH);
        int k  = isX ? o : (o - MH - 64);
        int i0 = isX ? i0x : i0y;
        const float* w = wgt[isX ? 0 : 1];
        int iw0 = i0 - WSUP;
        int t = (k * iw0) % M; if (t < 0) t += M;   // phase index k*i mod M (exact integers)
        int ks = k; if (ks < 0) ks += M;
        float re = 0.0f, im = 0.0f;
        #pragma unroll
        for (int d = 0; d < NW; d++) {
            float2 c = cis[t];
            re = fmaf(w[d], c.x, re);
            im = fmaf(w[d], c.y, im);
            t += ks; if (t >= M) t -= M;
        }
        if (isX) g_Gx[p * MH + o]        = make_float2(re, im);
        else     g_Gy[p * M + (o - MH)]  = make_float2(re, im);
    }
}

// ---------------------------------------------------------------- per-batch partial S
// S_b(k1,k2) = sum_q Gx_q(k1) * Gy_q(k2); point sum split into NCH chunks for parallelism.
__global__ void k_S() {
    int j1b = blockIdx.x * RJ;        // 13 row tiles
    int b   = blockIdx.y;             // 4 batches
    int pz  = blockIdx.z;             // 8 point chunks
    int tid = threadIdx.x;            // 160 threads (129 active in compute)
    __shared__ float2 sgx[PCH * RJ];

    int p0 = b * NP + pz * PCH;
    if (tid < PCH) {
        #pragma unroll
        for (int r = 0; r < RJ; r++)
            sgx[tid * RJ + r] = g_Gx[(p0 + tid) * MH + j1b + r];
    }
    __syncthreads();

    if (tid < M) {
        float2 acc[RJ];
        #pragma unroll
        for (int r = 0; r < RJ; r++) acc[r] = make_float2(0.0f, 0.0f);

        for (int pl = 0; pl < PCH; pl++) {
            float2 gy = __ldg(&g_Gy[(p0 + pl) * M + tid]);
            #pragma unroll
            for (int r = 0; r < RJ; r++) {
                float2 gx = sgx[pl * RJ + r];
                acc[r].x = fmaf(gx.x, gy.x, fmaf(-gx.y, gy.y, acc[r].x));
                acc[r].y = fmaf(gx.x, gy.y, fmaf( gx.y, gy.x, acc[r].y));
            }
        }
        #pragma unroll
        for (int r = 0; r < RJ; r++)
            g_Spart[pz * (NB * MH * M) + ((b * MH + j1b + r) * M + tid)] = acc[r];
    }
}

// ---------------------------------------------------------------- reduce partials + pack S with D
// D_c(k) = wfold * (pi/288) * exp(2*tau*|k|^2) * amp_c / (|k|^2 + (mu_c*shift_c)^2)
// (pi/288 = scale/M^2 * (pi/tau)^2 * 4*pi, tau = 12/M^2, L = 2*pi; mu0 = mu1 = 1)
__global__ void k_Sreduce_D(const float* __restrict__ s0, const float* __restrict__ s1,
                            const float* __restrict__ a0, const float* __restrict__ a1) {
    int idx = blockIdx.x * blockDim.x + threadIdx.x;   // over NB*MH*M
    if (idx >= NB * MH * M) return;

    float2 acc = make_float2(0.0f, 0.0f);
    #pragma unroll
    for (int c = 0; c < NCH; c++) {           // fixed order: deterministic
        float2 v = g_Spart[c * (NB * MH * M) + idx];
        acc.x += v.x; acc.y += v.y;
    }

    int kk = idx % (MH * M);                  // k-point index within one batch
    int j1 = kk / M;
    int j2 = kk - j1 * M;
    float k1 = (float)j1;
    float k2 = (float)(j2 - 64);
    float ks = k1 * k1 + k2 * k2;
    const float TAU  = (float)(12.0 / (129.0 * 129.0));
    const float PREF = (float)(3.14159265358979323846 / 288.0);
    float wf   = (j1 == 0) ? 1.0f : 2.0f;     // conjugate-symmetry fold weight
    float base = wf * PREF * expf(2.0f * TAU * ks);
    float m0 = s0[0];                          // mu0 * shift0, mu0 = 1
    float m1 = s1[0];                          // mu1 * shift1, mu1 = 1
    g_SD[idx] = make_float4(acc.x, acc.y,
                            base * a0[0] / (ks + m0 * m0),
                            base * a1[0] / (ks + m1 * m1));
}

// ---------------------------------------------------------------- energies (f32x2 packed pairs)
// e[b,p,c] = sum_k D_c(k) * ( Re(S conj(F)) - |F|^2 ),  F_p = Gx_p (x) Gy_p
// Points processed in pairs: (pp=2*pr, pp=2*pr+1) share one f32x2 lane pair.
#define PPB   8    // points per block
#define NPAIR 4    // point pairs per block
#define NWP   16   // warps per block (512 threads)
#define GYS   5    // padded float4 stride per j2 row (4 pairs + 1 pad; bank-conflict-free)
__global__ void __launch_bounds__(512, 2) k_energy(float* __restrict__ out) {
    int b     = blockIdx.x >> 6;
    int grp   = blockIdx.x & 63;
    int pbase = b * NP + grp * PPB;   // global point index of first point in group
    int tid   = threadIdx.x;          // 512 threads = 16 warps
    int lane  = tid & 31, w = tid >> 5;

    // packed pair tiles: float4 = (p0.x, p1.x, p0.y, p1.y) read back as ulonglong2
    __shared__ float4 sGxQ[MH * NPAIR];        // 4160 B
    __shared__ float4 sGyQ[M * GYS];           // 10320 B (entries pair 0..3 used)
    __shared__ float  wred[NWP][2 * PPB];

    for (int i = tid; i < MH * NPAIR; i += 512) {
        int r = i >> 2, pr = i & 3;
        float2 a = g_Gx[(pbase + 2 * pr)     * MH + r];
        float2 c = g_Gx[(pbase + 2 * pr + 1) * MH + r];
        sGxQ[i] = make_float4(a.x, c.x, a.y, c.y);
    }
    for (int i = tid; i < M * NPAIR; i += 512) {
        int j = i >> 2, pr = i & 3;
        float2 a = g_Gy[(pbase + 2 * pr)     * M + j];
        float2 c = g_Gy[(pbase + 2 * pr + 1) * M + j];
        sGyQ[j * GYS + pr] = make_float4(a.x, c.x, a.y, c.y);
    }
    __syncthreads();

    unsigned long long acc0[NPAIR], acc1[NPAIR];
    #pragma unroll
    for (int pr = 0; pr < NPAIR; pr++) { acc0[pr] = 0ULL; acc1[pr] = 0ULL; }

    const unsigned long long NEG1 = 0xBF800000BF800000ULL;   // packed (-1.0f, -1.0f)
    const float4* SDb = g_SD + b * MH * M;
    for (int r = w; r < MH; r += NWP) {           // row-per-warp
        unsigned long long gxX[NPAIR], gxY[NPAIR];
        #pragma unroll
        for (int pr = 0; pr < NPAIR; pr++) {
            ulonglong2 v = *reinterpret_cast<const ulonglong2*>(&sGxQ[r * NPAIR + pr]);
            gxX[pr] = v.x; gxY[pr] = v.y;
        }
        const float4* SDrow = SDb + r * M;
        for (int j2 = lane; j2 < M; j2 += 32) {    // coalesced LDG.128
            float4 SD = __ldg(&SDrow[j2]);         // (S.re, S.im, D0, D1)
            unsigned long long SXX = f2_pack(SD.x, SD.x);
            unsigned long long SYY = f2_pack(SD.y, SD.y);
            unsigned long long DP0 = f2_pack(SD.z, SD.z);
            unsigned long long DP1 = f2_pack(SD.w, SD.w);
            #pragma unroll
            for (int pr = 0; pr < NPAIR; pr++) {
                ulonglong2 gy = *reinterpret_cast<const ulonglong2*>(&sGyQ[j2 * GYS + pr]);
                // Fre = gx.x*gy.x - gx.y*gy.y ;  Fim = gx.x*gy.y + gx.y*gy.x
                unsigned long long t   = f2_mul(gxY[pr], gy.y);
                unsigned long long Fre = f2_fma(t, NEG1, f2_mul(gxX[pr], gy.x));
                unsigned long long Fim = f2_fma(gxX[pr], gy.y, f2_mul(gxY[pr], gy.x));
                // u = Fre*Sx + Fim*Sy - (Fre^2 + Fim^2)
                unsigned long long P = f2_fma(Fre, SXX, f2_mul(Fim, SYY));
                unsigned long long Q = f2_fma(Fre, Fre, f2_mul(Fim, Fim));
                unsigned long long u = f2_fma(Q, NEG1, P);
                acc0[pr] = f2_fma(DP0, u, acc0[pr]);
                acc1[pr] = f2_fma(DP1, u, acc1[pr]);
            }
        }
    }

    #pragma unroll
    for (int pr = 0; pr < NPAIR; pr++) {
        float a0lo, a0hi, a1lo, a1hi;
        f2_unpack(a0lo, a0hi, acc0[pr]);
        f2_unpack(a1lo, a1hi, acc1[pr]);
        #pragma unroll
        for (int s = 16; s > 0; s >>= 1) {
            a0lo += __shfl_down_sync(0xffffffffu, a0lo, s);
            a0hi += __shfl_down_sync(0xffffffffu, a0hi, s);
            a1lo += __shfl_down_sync(0xffffffffu, a1lo, s);
            a1hi += __shfl_down_sync(0xffffffffu, a1hi, s);
        }
        if (lane == 0) {
            int pp0 = 2 * pr, pp1 = 2 * pr + 1;
            wred[w][2 * pp0]     = a0lo;  wred[w][2 * pp0 + 1] = a1lo;
            wred[w][2 * pp1]     = a0hi;  wred[w][2 * pp1 + 1] = a1hi;
        }
    }
    __syncthreads();
    if (tid < 2 * PPB) {                       // deterministic tree finish (no float atomics)
        float s = 0.0f;
        #pragma unroll
        for (int ww = 0; ww < NWP; ww++) s += wred[ww][tid];
        out[pbase * 2 + tid] = s;              // tid = pp*2 + c
    }
}

// ---------------------------------------------------------------- launch
extern "C" void kernel_launch(void* const* d_in, const int* in_sizes, int n_in,
                              void* d_out, int out_size) {
    const float* x  = (const float*)d_in[0];  // [4,512,2]
    const float* s0 = (const float*)d_in[1];  // shift0 [1]
    const float* s1 = (const float*)d_in[2];  // shift1 [1]
    const float* a0 = (const float*)d_in[3];  // amp0   [1]
    const float* a1 = (const float*)d_in[4];  // amp1   [1]
    float* out = (float*)d_out;               // [4,512,2]

    k_spectra<<<NPTS, 128>>>(x);
    k_S<<<dim3(13, NB, NCH), 160>>>();
    k_Sreduce_D<<<(NB * MH * M + 255) / 256, 256>>>(s0, s1, a0, a1);
    k_energy<<<NB * 64, 512>>>(out);
}

// round 15
// speedup vs baseline: 1.0602x; 1.0602x over previous
#include <cuda_runtime.h>
#include <math.h>

// Problem constants
#define M    129         // mesh points per dim (odd)
#define MH   65          // half-spectrum rows: k1 = 0..64
#define NB   4           // batch
#define NP   512         // points per batch
#define NPTS (NB*NP)     // 2048
#define WSUP 7           // gaussian support half-width (tail at d=8 ~ 1e-23)
#define NW   15          // taps = 2*WSUP+1
#define RJ   5           // k1 rows per k_S block (13*5 = 65)
#define PCH  64          // points per k_S chunk (512/64 = 8 chunks)
#define NCH  8

// Scratch (__device__ globals: no allocations allowed)
__device__ float2 g_Gx[NPTS*MH];          // per-point x-spectrum, k1 = 0..64
__device__ float2 g_Gy[NPTS*M];           // per-point y-spectrum, k2 = -64..64 (j2 = k2+64)
__device__ float2 g_Spart[NCH*NB*MH*M];   // partial per-batch spectrum sums (8 chunks)
__device__ float4 g_SD[NB*MH*M + 64];     // packed (S.re,S.im,D0,D1); +64 pad for uniform-trip reads

// ---------------------------------------------------------------- f32x2 helpers
__device__ __forceinline__ unsigned long long f2_fma(unsigned long long a, unsigned long long b,
                                                     unsigned long long c) {
    unsigned long long d;
    asm("fma.rn.f32x2 %0, %1, %2, %3;" : "=l"(d) : "l"(a), "l"(b), "l"(c));
    return d;
}
__device__ __forceinline__ unsigned long long f2_mul(unsigned long long a, unsigned long long b) {
    unsigned long long d;
    asm("mul.rn.f32x2 %0, %1, %2;" : "=l"(d) : "l"(a), "l"(b));
    return d;
}
__device__ __forceinline__ unsigned long long f2_pack(float lo, float hi) {
    unsigned long long d;
    asm("mov.b64 %0, {%1, %2};" : "=l"(d) : "f"(lo), "f"(hi));
    return d;
}
__device__ __forceinline__ void f2_unpack(float& lo, float& hi, unsigned long long v) {
    asm("mov.b64 {%0, %1}, %2;" : "=f"(lo), "=f"(hi) : "l"(v));
}

// ---------------------------------------------------------------- per-point 1D spectra
__device__ __forceinline__ float gper(float x) {
    const float INV4 = (float)(129.0 * 129.0 / 48.0);   // 1/(4*tau), tau = 12/M^2
    const float L    = (float)(2.0 * 3.14159265358979323846);
    return expf(-x * x * INV4)
         + expf(-(x - L) * (x - L) * INV4)
         + expf(-(x + L) * (x + L) * INV4);
}

__global__ void k_spectra(const float* __restrict__ X) {
    int p   = blockIdx.x;       // global point index 0..2047
    int tid = threadIdx.x;      // 128 threads
    __shared__ float2 cis[M];   // exp(-2*pi*i*t/M)
    __shared__ float  wgt[2][NW];

    for (int t = tid; t < M; t += 128) {
        float ang = (float)t * (float)(-2.0 * 3.14159265358979323846 / 129.0);
        float s, c;
        sincosf(ang, &s, &c);
        cis[t] = make_float2(c, s);
    }

    float x0 = X[2 * p];
    float y0 = X[2 * p + 1];
    const float H    = (float)(2.0 * 3.14159265358979323846 / 129.0);
    const float INVH = (float)(129.0 / (2.0 * 3.14159265358979323846));
    int i0x = (int)floorf(x0 * INVH + 0.5f);
    int i0y = (int)floorf(y0 * INVH + 0.5f);

    if (tid < 2 * NW) {
        int dim = tid / NW;
        int d   = tid - dim * NW;
        float xv = dim ? y0 : x0;
        int   i0 = dim ? i0y : i0x;
        int i  = i0 - WSUP + d;
        int iw = i % M; if (iw < 0) iw += M;        // wrapped grid index (matches reference arg)
        wgt[dim][d] = gper(xv - (float)iw * H);
    }
    __syncthreads();

    // 65 x-outputs (k=0..64) + 129 y-outputs (k=-64..64)
    for (int o = tid; o < MH + M; o += 128) {
        bool isX = (o < MH);
        int k  = isX ? o : (o - MH - 64);
        int i0 = isX ? i0x : i0y;
        const float* w = wgt[isX ? 0 : 1];
        int iw0 = i0 - WSUP;
        int t = (k * iw0) % M; if (t < 0) t += M;   // phase index k*i mod M (exact integers)
        int ks = k; if (ks < 0) ks += M;
        float re = 0.0f, im = 0.0f;
        #pragma unroll
        for (int d = 0; d < NW; d++) {
            float2 c = cis[t];
            re = fmaf(w[d], c.x, re);
            im = fmaf(w[d], c.y, im);
            t += ks; if (t >= M) t -= M;
        }
        if (isX) g_Gx[p * MH + o]        = make_float2(re, im);
        else     g_Gy[p * M + (o - MH)]  = make_float2(re, im);
    }
}

// ---------------------------------------------------------------- per-batch partial S
// S_b(k1,k2) = sum_q Gx_q(k1) * Gy_q(k2); point sum split into NCH chunks for parallelism.
__global__ void k_S() {
    int j1b = blockIdx.x * RJ;        // 13 row tiles
    int b   = blockIdx.y;             // 4 batches
    int pz  = blockIdx.z;             // 8 point chunks
    int tid = threadIdx.x;            // 160 threads (129 active in compute)
    __shared__ float2 sgx[PCH * RJ];

    int p0 = b * NP + pz * PCH;
    if (tid < PCH) {
        #pragma unroll
        for (int r = 0; r < RJ; r++)
            sgx[tid * RJ + r] = g_Gx[(p0 + tid) * MH + j1b + r];
    }
    __syncthreads();

    if (tid < M) {
        float2 acc[RJ];
        #pragma unroll
        for (int r = 0; r < RJ; r++) acc[r] = make_float2(0.0f, 0.0f);

        for (int pl = 0; pl < PCH; pl++) {
            float2 gy = __ldg(&g_Gy[(p0 + pl) * M + tid]);
            #pragma unroll
            for (int r = 0; r < RJ; r++) {
                float2 gx = sgx[pl * RJ + r];
                acc[r].x = fmaf(gx.x, gy.x, fmaf(-gx.y, gy.y, acc[r].x));
                acc[r].y = fmaf(gx.x, gy.y, fmaf( gx.y, gy.x, acc[r].y));
            }
        }
        #pragma unroll
        for (int r = 0; r < RJ; r++)
            g_Spart[pz * (NB * MH * M) + ((b * MH + j1b + r) * M + tid)] = acc[r];
    }
}

// ---------------------------------------------------------------- reduce partials + pack S with D
// D_c(k) = wfold * (pi/288) * exp(2*tau*|k|^2) * amp_c / (|k|^2 + (mu_c*shift_c)^2)
// (pi/288 = scale/M^2 * (pi/tau)^2 * 4*pi, tau = 12/M^2, L = 2*pi; mu0 = mu1 = 1)
__global__ void k_Sreduce_D(const float* __restrict__ s0, const float* __restrict__ s1,
                            const float* __restrict__ a0, const float* __restrict__ a1) {
    int idx = blockIdx.x * blockDim.x + threadIdx.x;   // over NB*MH*M
    if (idx >= NB * MH * M) return;

    float2 acc = make_float2(0.0f, 0.0f);
    #pragma unroll
    for (int c = 0; c < NCH; c++) {           // fixed order: deterministic
        float2 v = g_Spart[c * (NB * MH * M) + idx];
        acc.x += v.x; acc.y += v.y;
    }

    int kk = idx % (MH * M);                  // k-point index within one batch
    int j1 = kk / M;
    int j2 = kk - j1 * M;
    float k1 = (float)j1;
    float k2 = (float)(j2 - 64);
    float ks = k1 * k1 + k2 * k2;
    const float TAU  = (float)(12.0 / (129.0 * 129.0));
    const float PREF = (float)(3.14159265358979323846 / 288.0);
    float wf   = (j1 == 0) ? 1.0f : 2.0f;     // conjugate-symmetry fold weight
    float base = wf * PREF * expf(2.0f * TAU * ks);
    float m0 = s0[0];                          // mu0 * shift0, mu0 = 1
    float m1 = s1[0];                          // mu1 * shift1, mu1 = 1
    g_SD[idx] = make_float4(acc.x, acc.y,
                            base * a0[0] / (ks + m0 * m0),
                            base * a1[0] / (ks + m1 * m1));
}

// ---------------------------------------------------------------- energies (f32x2 packed pairs)
// e[b,p,c] = sum_k D_c(k) * ( Re(S conj(F)) - |F|^2 ),  F_p = Gx_p (x) Gy_p
// Points processed in pairs: (pp=2*pr, pp=2*pr+1) share one f32x2 lane pair.
// Inner j2 loop padded to a UNIFORM 5 iterations (j2 = lane + 32*it, up to 159):
// pad region has gy == 0 => Fre = Fim = 0 => u == 0 exactly, so any finite SD value
// contributes nothing. g_SD is over-allocated (+64) so padded LDGs stay in bounds.
#define PPB   8    // points per block
#define NPAIR 4    // point pairs per block
#define NWP   16   // warps per block (512 threads)
#define GYS   5    // padded float4 stride per j2 row (4 pairs + 1 pad; bank-conflict-free)
#define J2PAD 160  // padded j2 range: 5 uniform iterations * 32 lanes
__global__ void __launch_bounds__(512, 2) k_energy(float* __restrict__ out) {
    int b     = blockIdx.x >> 6;
    int grp   = blockIdx.x & 63;
    int pbase = b * NP + grp * PPB;   // global point index of first point in group
    int tid   = threadIdx.x;          // 512 threads = 16 warps
    int lane  = tid & 31, w = tid >> 5;

    // packed pair tiles: float4 = (p0.x, p1.x, p0.y, p1.y) read back as ulonglong2
    __shared__ float4 sGxQ[MH * NPAIR];        // 4160 B
    __shared__ float4 sGyQ[J2PAD * GYS];       // 12800 B; rows >= M are zero
    __shared__ float  wred[NWP][2 * PPB];

    for (int i = tid; i < MH * NPAIR; i += 512) {
        int r = i >> 2, pr = i & 3;
        float2 a = g_Gx[(pbase + 2 * pr)     * MH + r];
        float2 c = g_Gx[(pbase + 2 * pr + 1) * MH + r];
        sGxQ[i] = make_float4(a.x, c.x, a.y, c.y);
    }
    for (int i = tid; i < J2PAD * NPAIR; i += 512) {
        int j = i >> 2, pr = i & 3;
        if (j < M) {
            float2 a = g_Gy[(pbase + 2 * pr)     * M + j];
            float2 c = g_Gy[(pbase + 2 * pr + 1) * M + j];
            sGyQ[j * GYS + pr] = make_float4(a.x, c.x, a.y, c.y);
        } else {
            sGyQ[j * GYS + pr] = make_float4(0.0f, 0.0f, 0.0f, 0.0f);  // pad: exact zero
        }
    }
    __syncthreads();

    unsigned long long acc0[NPAIR], acc1[NPAIR];
    #pragma unroll
    for (int pr = 0; pr < NPAIR; pr++) { acc0[pr] = 0ULL; acc1[pr] = 0ULL; }

    const unsigned long long NEG1 = 0xBF800000BF800000ULL;   // packed (-1.0f, -1.0f)
    const float4* SDb = g_SD + b * MH * M;
    for (int r = w; r < MH; r += NWP) {           // row-per-warp
        unsigned long long gxX[NPAIR], gxY[NPAIR];
        #pragma unroll
        for (int pr = 0; pr < NPAIR; pr++) {
            ulonglong2 v = *reinterpret_cast<const ulonglong2*>(&sGxQ[r * NPAIR + pr]);
            gxX[pr] = v.x; gxY[pr] = v.y;
        }
        const float4* SDrow = SDb + r * M;
        #pragma unroll
        for (int it = 0; it < 5; it++) {           // uniform trip count -> batched loads
            int j2 = lane + it * 32;               // 0..159; >=129 is zero-pad region
            float4 SD = __ldg(&SDrow[j2]);         // padded g_SD keeps this in bounds
            unsigned long long SXX = f2_pack(SD.x, SD.x);
            unsigned long long SYY = f2_pack(SD.y, SD.y);
            unsigned long long DP0 = f2_pack(SD.z, SD.z);
            unsigned long long DP1 = f2_pack(SD.w, SD.w);
            #pragma unroll
            for (int pr = 0; pr < NPAIR; pr++) {
                ulonglong2 gy = *reinterpret_cast<const ulonglong2*>(&sGyQ[j2 * GYS + pr]);
                // Fre = gx.x*gy.x - gx.y*gy.y ;  Fim = gx.x*gy.y + gx.y*gy.x
                unsigned long long t   = f2_mul(gxY[pr], gy.y);
                unsigned long long Fre = f2_fma(t, NEG1, f2_mul(gxX[pr], gy.x));
                unsigned long long Fim = f2_fma(gxX[pr], gy.y, f2_mul(gxY[pr], gy.x));
                // u = Fre*Sx + Fim*Sy - (Fre^2 + Fim^2)
                unsigned long long P = f2_fma(Fre, SXX, f2_mul(Fim, SYY));
                unsigned long long Q = f2_fma(Fre, Fre, f2_mul(Fim, Fim));
                unsigned long long u = f2_fma(Q, NEG1, P);
                acc0[pr] = f2_fma(DP0, u, acc0[pr]);
                acc1[pr] = f2_fma(DP1, u, acc1[pr]);
            }
        }
    }

    #pragma unroll
    for (int pr = 0; pr < NPAIR; pr++) {
        float a0lo, a0hi, a1lo, a1hi;
        f2_unpack(a0lo, a0hi, acc0[pr]);
        f2_unpack(a1lo, a1hi, acc1[pr]);
        #pragma unroll
        for (int s = 16; s > 0; s >>= 1) {
            a0lo += __shfl_down_sync(0xffffffffu, a0lo, s);
            a0hi += __shfl_down_sync(0xffffffffu, a0hi, s);
            a1lo += __shfl_down_sync(0xffffffffu, a1lo, s);
            a1hi += __shfl_down_sync(0xffffffffu, a1hi, s);
        }
        if (lane == 0) {
            int pp0 = 2 * pr, pp1 = 2 * pr + 1;
            wred[w][2 * pp0]     = a0lo;  wred[w][2 * pp0 + 1] = a1lo;
            wred[w][2 * pp1]     = a0hi;  wred[w][2 * pp1 + 1] = a1hi;
        }
    }
    __syncthreads();
    if (tid < 2 * PPB) {                       // deterministic tree finish (no float atomics)
        float s = 0.0f;
        #pragma unroll
        for (int ww = 0; ww < NWP; ww++) s += wred[ww][tid];
        out[pbase * 2 + tid] = s;              // tid = pp*2 + c
    }
}

// ---------------------------------------------------------------- launch
extern "C" void kernel_launch(void* const* d_in, const int* in_sizes, int n_in,
                              void* d_out, int out_size) {
    const float* x  = (const float*)d_in[0];  // [4,512,2]
    const float* s0 = (const float*)d_in[1];  // shift0 [1]
    const float* s1 = (const float*)d_in[2];  // shift1 [1]
    const float* a0 = (const float*)d_in[3];  // amp0   [1]
    const float* a1 = (const float*)d_in[4];  // amp1   [1]
    float* out = (float*)d_out;               // [4,512,2]

    k_spectra<<<NPTS, 128>>>(x);
    k_S<<<dim3(13, NB, NCH), 160>>>();
    k_Sreduce_D<<<(NB * MH * M + 255) / 256, 256>>>(s0, s1, a0, a1);
    k_energy<<<NB * 64, 512>>>(out);
}